// round 11
// baseline (speedup 1.0000x reference)
#include <cuda_runtime.h>
#include <cub/cub.cuh>
#include <stdint.h>

#define Bn 2
#define Nn 4096
#define Mn 128
#define RAD 0.1f
#define R2  0.01f
#define MAXC 8192   // fast-path cell-count limit (this input: 1000)

// Output layout (flattened, concatenated in reference return order, all f32)
#define OFF_IDXS 0
#define OFF_NBR  (Bn*Nn)                       // 8192
#define OFF_LOCS (OFF_NBR + Bn*Nn*Mn)          // 1056768
#define OFF_DATA (OFF_LOCS + Bn*Nn*3)          // 1081344

// Scratch (no runtime allocations allowed)
__device__ uint32_t g_keys[Bn*Nn];   // sorted (cell<<12 | idx) per batch
__device__ float4   g_locs[Bn*Nn];   // sorted locs, .w = |p|^2
__device__ int4     g_grid[Bn];      // {g0, g1, g2, unused}

typedef cub::BlockRadixSort<uint32_t, 1024, 4, cub::NullType, 5> Sorter;
typedef cub::BlockScan<int, 1024> Scan;

struct FastPath {
    typename Scan::TempStorage scan_ts;
    int      start[MAXC];    // pristine segment starts
    int      cursor[MAXC];   // hist -> scatter cursor -> segment end
    uint32_t keys[Nn];
};
union PrepSmem {
    typename Sorter::TempStorage sort_ts;   // fallback (ncells > MAXC)
    FastPath fp;
};

// Emit all gather outputs for one particle landing at sorted position p.
// sq computed ONCE from the loaded coords (rn-exact), used by k_neighbors on
// both sides of d2 — matches the reference's single sq computation.
__device__ __forceinline__ void emit_particle(
    int b, int p, uint32_t key,
    const float* __restrict__ locs, const float* __restrict__ data,
    float* __restrict__ out, uint32_t* __restrict__ gk)
{
    int ord = (int)(key & 4095u);
    gk[p] = key;

    const float* lp = locs + (size_t)(b*Nn + ord) * 3;
    float x = lp[0], y = lp[1], z = lp[2];
    float sq = __fadd_rn(__fadd_rn(__fmul_rn(x, x), __fmul_rn(y, y)),
                         __fmul_rn(z, z));
    int gid = b * Nn + p;
    g_locs[gid] = make_float4(x, y, z, sq);

    out[OFF_IDXS + gid] = (float)ord;
    float* lout = out + OFF_LOCS + (size_t)gid * 3;
    lout[0] = x; lout[1] = y; lout[2] = z;

    const float4* dp = (const float4*)(data + (size_t)(b*Nn + ord) * 16);
    float4* dq = (float4*)(out + OFF_DATA + (size_t)gid * 16);
    #pragma unroll
    for (int q = 0; q < 4; q++) dq[q] = dp[q];
}

// ---------------------------------------------------------------------------
// Kernel 1 (fully fused): bounds -> grid math (rn-exact, reference-identical)
// -> packed keys -> smem counting sort (hist + scan + atomic scatter +
// PARALLEL rank-in-segment on full unique keys == reference stable argsort)
// -> gather outputs emitted in place. CUB radix fallback for ncells > MAXC.
// ---------------------------------------------------------------------------
__global__ __launch_bounds__(1024, 1) void k_prep(const float* __restrict__ locs,
                                                  const float* __restrict__ data,
                                                  float* __restrict__ out) {
    extern __shared__ char dynsm[];
    PrepSmem* sm = reinterpret_cast<PrepSmem*>(dynsm);

    int b = blockIdx.x;
    const float* L = locs + (size_t)b * Nn * 3;
    int t = threadIdx.x, lane = t & 31, warp = t >> 5;

    __shared__ float wmn[3][32], wmx[3][32];
    __shared__ float s_lo[3], s_gdm1[3];
    __shared__ int   s_strd[3], s_ncells, s_cellbits;

    float mn[3] = {1e30f, 1e30f, 1e30f};
    float mx[3] = {-1e30f, -1e30f, -1e30f};
    for (int i = t; i < Nn; i += 1024) {
        #pragma unroll
        for (int d = 0; d < 3; d++) {
            float v = L[i*3+d];
            mn[d] = fminf(mn[d], v); mx[d] = fmaxf(mx[d], v);
        }
    }
    #pragma unroll
    for (int o = 16; o; o >>= 1) {
        #pragma unroll
        for (int d = 0; d < 3; d++) {
            mn[d] = fminf(mn[d], __shfl_xor_sync(0xffffffffu, mn[d], o));
            mx[d] = fmaxf(mx[d], __shfl_xor_sync(0xffffffffu, mx[d], o));
        }
    }
    if (lane == 0) {
        #pragma unroll
        for (int d = 0; d < 3; d++) { wmn[d][warp] = mn[d]; wmx[d][warp] = mx[d]; }
    }
    __syncthreads();
    if (t < 32) {
        #pragma unroll
        for (int d = 0; d < 3; d++) { mn[d] = wmn[d][t]; mx[d] = wmx[d][t]; }
        #pragma unroll
        for (int o = 16; o; o >>= 1) {
            #pragma unroll
            for (int d = 0; d < 3; d++) {
                mn[d] = fminf(mn[d], __shfl_xor_sync(0xffffffffu, mn[d], o));
                mx[d] = fmaxf(mx[d], __shfl_xor_sync(0xffffffffu, mx[d], o));
            }
        }
        if (t == 0) {
            float gdv[3];
            #pragma unroll
            for (int d = 0; d < 3; d++) {
                float l = mn[d], u = mx[d];
                float r = __fdiv_rn(__fsub_rn(u, l), RAD);
                r = fminf(fmaxf(r, 0.0f), 96.0f);
                float gdf = ceilf(r);
                float c = __fmul_rn(__fadd_rn(l, u), 0.5f);
                s_lo[d] = __fsub_rn(c, __fmul_rn(__fmul_rn(gdf, RAD), 0.5f));
                float gd = fmaxf(gdf, 1.0f);
                gdv[d] = gd;
                s_gdm1[d] = gd - 1.0f;
            }
            int g0 = (int)gdv[0], g1 = (int)gdv[1], g2 = (int)gdv[2];
            s_strd[0] = g1 * g2; s_strd[1] = g2; s_strd[2] = 1;
            int ncells = g0 * g1 * g2;
            s_ncells = ncells;
            s_cellbits = (ncells <= 1) ? 0 : (32 - __clz(ncells - 1));
            g_grid[b] = make_int4(g0, g1, g2, 0);
        }
    }
    __syncthreads();

    // this thread's 4 blocked keys (globally ascending index order)
    uint32_t tk[4];
    #pragma unroll
    for (int k = 0; k < 4; k++) {
        int i = t * 4 + k;
        int flat = 0;
        #pragma unroll
        for (int d = 0; d < 3; d++) {
            float c = floorf(__fdiv_rn(__fsub_rn(L[i*3+d], s_lo[d]), RAD));
            c = fminf(fmaxf(c, 0.0f), s_gdm1[d]);
            flat += (int)c * s_strd[d];
        }
        tk[k] = ((uint32_t)flat << 12) | (uint32_t)i;
    }
    int ncells = s_ncells, cellbits = s_cellbits;
    __syncthreads();

    uint32_t* gk = g_keys + b * Nn;

    if (cellbits == 0) {
        // single cell: blocked order already == stable order
        #pragma unroll
        for (int k = 0; k < 4; k++)
            emit_particle(b, t*4 + k, tk[k], locs, data, out, gk);
        return;
    }

    if (ncells <= MAXC) {
        // ---- fast path: smem counting sort + parallel segment rank ----
        int*      start  = sm->fp.start;
        int*      cursor = sm->fp.cursor;
        uint32_t* skeys  = sm->fp.keys;

        for (int c = t; c < ncells; c += 1024) cursor[c] = 0;
        __syncthreads();
        #pragma unroll
        for (int k = 0; k < 4; k++) atomicAdd(&cursor[tk[k] >> 12], 1);
        __syncthreads();

        // exclusive scan of counts -> start; reset cursor to start
        int items = (ncells + 1023) >> 10;
        int base = t * items;
        int lsum = 0;
        for (int k = 0; k < items; k++) {
            int c = base + k;
            if (c < ncells) lsum += cursor[c];
        }
        int run;
        Scan(sm->fp.scan_ts).ExclusiveSum(lsum, run);
        __syncthreads();
        for (int k = 0; k < items; k++) {
            int c = base + k;
            if (c < ncells) {
                int h = cursor[c];       // count (only this thread touches c)
                start[c]  = run;
                cursor[c] = run;         // scatter cursor
                run += h;
            }
        }
        __syncthreads();

        // scatter into cell segments (order within cell arbitrary)
        #pragma unroll
        for (int k = 0; k < 4; k++) {
            int pos = atomicAdd(&cursor[tk[k] >> 12], 1);
            skeys[pos] = tk[k];
        }
        __syncthreads();   // after this, cursor[c] == segment end

        // parallel rank within segment + fused gather emit.
        // keys unique -> segstart + (#smaller in segment) is exact stable pos.
        #pragma unroll
        for (int k = 0; k < 4; k++) {
            int p = t * 4 + k;
            uint32_t key = skeys[p];
            int c = (int)(key >> 12);
            int s = start[c], e = cursor[c];
            int r = 0;
            for (int q = s; q < e; q++) r += (skeys[q] < key);
            emit_particle(b, s + r, key, locs, data, out, gk);
        }
    } else {
        // ---- fallback: CUB radix over cell bits (stable passes) ----
        Sorter(sm->sort_ts).Sort(tk, 12, 12 + cellbits);
        #pragma unroll
        for (int k = 0; k < 4; k++)
            emit_particle(b, t*4 + k, tk[k], locs, data, out, gk);
    }
}

// ---------------------------------------------------------------------------
// Kernel 2: neighbor lists with cell pruning. 64 particles per block (one
// warp scans 2 particles) -> 128 blocks, halved L2 staging traffic vs 256.
// 9 (dx,dy) segments found by parallel binary search on sorted keys; segments
// visited in ascending cell-id (== ascending sorted index) order, realizing
// the reference's "first 128 in-radius, ascending" exactly.
// ---------------------------------------------------------------------------
__global__ __launch_bounds__(1024, 1) void k_neighbors(float* __restrict__ out) {
    extern __shared__ char smem[];
    float4*   shl = (float4*)smem;                 // 65536 B
    uint32_t* shk = (uint32_t*)(smem + Nn * 16);   // 16384 B
    int b    = blockIdx.x >> 6;     // 64 tiles of 64 particles per batch
    int tile = blockIdx.x & 63;
    const float4*   gl = g_locs + b * Nn;
    const uint32_t* gk = g_keys + b * Nn;
    for (int i = threadIdx.x; i < Nn; i += 1024) { shl[i] = gl[i]; shk[i] = gk[i]; }
    __syncthreads();

    int4 G = g_grid[b];
    int g0 = G.x, g1 = G.y, g2 = G.z;

    int warp = threadIdx.x >> 5;
    int lane = threadIdx.x & 31;
    unsigned lt = (1u << lane) - 1u;

    #pragma unroll 1
    for (int pi = 0; pi < 2; pi++) {
        int i = tile * 64 + pi * 32 + warp;

        uint32_t mykey = shk[i];
        int cell = (int)(mykey >> 12);
        int cz = cell % g2;
        int t2 = cell / g2;
        int cy = t2 % g1;
        int cx = t2 / g1;

        // lanes 0..17: binary search the 9 segment bounds (2 per segment)
        int res = 0;
        if (lane < 18) {
            int s  = lane >> 1;
            int dx = s / 3 - 1, dy = s % 3 - 1;
            int nx = cx + dx, ny = cy + dy;
            if (nx >= 0 && nx < g0 && ny >= 0 && ny < g1) {
                int base = (nx * g1 + ny) * g2;
                int zlo = max(cz - 1, 0), zhi = min(cz + 1, g2 - 1);
                uint32_t target = ((uint32_t)((lane & 1) ? (base + zhi + 1)
                                                         : (base + zlo))) << 12;
                int lo = 0, hi = Nn;
                while (lo < hi) {
                    int mid = (lo + hi) >> 1;
                    if (shk[mid] < target) lo = mid + 1; else hi = mid;
                }
                res = lo;
            }
        }

        float4 me = shl[i];
        float* nout = out + OFF_NBR + (size_t)(b*Nn + i) * Mn;

        int count = 0;
        #pragma unroll 1
        for (int s = 0; s < 9; s++) {
            int lo = __shfl_sync(0xffffffffu, res, 2*s);
            int hi = __shfl_sync(0xffffffffu, res, 2*s + 1);
            for (int j0 = lo; j0 < hi; j0 += 32) {
                int j = j0 + lane;
                bool m = false;
                if (j < hi) {
                    float4 o = shl[j];
                    float dot = __fadd_rn(__fadd_rn(__fmul_rn(me.x, o.x),
                                                    __fmul_rn(me.y, o.y)),
                                          __fmul_rn(me.z, o.z));
                    float d2 = __fsub_rn(__fadd_rn(me.w, o.w),
                                         __fmul_rn(2.0f, dot));
                    m = (d2 <= R2);
                }
                unsigned bal = __ballot_sync(0xffffffffu, m);
                if (m) {
                    int pos = count + __popc(bal & lt);
                    if (pos < Mn) nout[pos] = (float)j;
                }
                count += __popc(bal);
                if (count >= Mn) goto fill;
            }
        }
fill:
        for (int p = min(count, Mn) + lane; p < Mn; p += 32) nout[p] = -1.0f;
    }
}

// ---------------------------------------------------------------------------
extern "C" void kernel_launch(void* const* d_in, const int* in_sizes, int n_in,
                              void* d_out, int out_size) {
    const float* locs = (const float*)d_in[0];
    const float* data = (const float*)d_in[1];
    float* out = (float*)d_out;

    cudaFuncSetAttribute(k_prep,
                         cudaFuncAttributeMaxDynamicSharedMemorySize,
                         (int)sizeof(PrepSmem));
    cudaFuncSetAttribute(k_neighbors,
                         cudaFuncAttributeMaxDynamicSharedMemorySize,
                         Nn * 16 + Nn * 4);

    k_prep<<<Bn, 1024, sizeof(PrepSmem)>>>(locs, data, out);
    k_neighbors<<<Bn * (Nn / 64), 1024, Nn * 16 + Nn * 4>>>(out);
}

// round 13
// speedup vs baseline: 1.9808x; 1.9808x over previous
#include <cuda_runtime.h>
#include <cub/cub.cuh>
#include <stdint.h>

#define Bn 2
#define Nn 4096
#define Mn 128
#define RAD 0.1f
#define R2  0.01f
#define MAXC 8192   // fast-path cell-count limit (this input: 1000)

// Output layout (flattened, concatenated in reference return order, all f32)
#define OFF_IDXS 0
#define OFF_NBR  (Bn*Nn)                       // 8192
#define OFF_LOCS (OFF_NBR + Bn*Nn*Mn)          // 1056768
#define OFF_DATA (OFF_LOCS + Bn*Nn*3)          // 1081344

// Scratch (no runtime allocations allowed)
__device__ uint32_t g_keys[Bn*Nn];   // sorted (cell<<12 | idx) per batch
__device__ float4   g_locs[Bn*Nn];   // sorted locs, .w = |p|^2
__device__ int4     g_grid[Bn];      // {g0, g1, g2, unused}

typedef cub::BlockRadixSort<uint32_t, 1024, 4, cub::NullType, 5> Sorter;
typedef cub::BlockScan<int, 1024> Scan;

struct FastPath {
    typename Scan::TempStorage scan_ts;
    int      start[MAXC];    // pristine segment starts
    int      cursor[MAXC];   // hist -> scatter cursor -> segment end
    uint32_t keys[Nn];
};
union PrepSmem {
    typename Sorter::TempStorage sort_ts;   // fallback (ncells > MAXC)
    FastPath fp;
};

// ---------------------------------------------------------------------------
// Kernel 1: bounds -> grid math (rn-exact, reference-identical) -> packed
// keys -> smem counting sort (hist + scan + atomic scatter + PARALLEL
// rank-in-segment on full unique keys == reference stable argsort).
// Single global read pass: each thread loads its 4 blocked particles once
// (3 coalesced float4s), reused for both the min/max reduce and keygen.
// ---------------------------------------------------------------------------
__global__ __launch_bounds__(1024, 1) void k_prep(const float* __restrict__ locs) {
    extern __shared__ char dynsm[];
    PrepSmem* sm = reinterpret_cast<PrepSmem*>(dynsm);

    int b = blockIdx.x;
    const float* L = locs + (size_t)b * Nn * 3;
    int t = threadIdx.x, lane = t & 31, warp = t >> 5;

    __shared__ float wmn[3][32], wmx[3][32];
    __shared__ float s_lo[3], s_gdm1[3];
    __shared__ int   s_strd[3], s_ncells, s_cellbits;

    // --- single coalesced load of this thread's 4 blocked particles ---
    const float4* Lv = (const float4*)L;
    float4 va = Lv[t*3 + 0], vb = Lv[t*3 + 1], vc = Lv[t*3 + 2];
    float px[4] = {va.x, va.w, vb.z, vc.y};
    float py[4] = {va.y, vb.x, vb.w, vc.z};
    float pz[4] = {va.z, vb.y, vc.x, vc.w};

    // --- min/max reduce from registers ---
    float mn[3], mx[3];
    mn[0] = fminf(fminf(px[0], px[1]), fminf(px[2], px[3]));
    mx[0] = fmaxf(fmaxf(px[0], px[1]), fmaxf(px[2], px[3]));
    mn[1] = fminf(fminf(py[0], py[1]), fminf(py[2], py[3]));
    mx[1] = fmaxf(fmaxf(py[0], py[1]), fmaxf(py[2], py[3]));
    mn[2] = fminf(fminf(pz[0], pz[1]), fminf(pz[2], pz[3]));
    mx[2] = fmaxf(fmaxf(pz[0], pz[1]), fmaxf(pz[2], pz[3]));
    #pragma unroll
    for (int o = 16; o; o >>= 1) {
        #pragma unroll
        for (int d = 0; d < 3; d++) {
            mn[d] = fminf(mn[d], __shfl_xor_sync(0xffffffffu, mn[d], o));
            mx[d] = fmaxf(mx[d], __shfl_xor_sync(0xffffffffu, mx[d], o));
        }
    }
    if (lane == 0) {
        #pragma unroll
        for (int d = 0; d < 3; d++) { wmn[d][warp] = mn[d]; wmx[d][warp] = mx[d]; }
    }
    __syncthreads();
    if (t < 32) {
        #pragma unroll
        for (int d = 0; d < 3; d++) { mn[d] = wmn[d][t]; mx[d] = wmx[d][t]; }
        #pragma unroll
        for (int o = 16; o; o >>= 1) {
            #pragma unroll
            for (int d = 0; d < 3; d++) {
                mn[d] = fminf(mn[d], __shfl_xor_sync(0xffffffffu, mn[d], o));
                mx[d] = fmaxf(mx[d], __shfl_xor_sync(0xffffffffu, mx[d], o));
            }
        }
        if (t == 0) {
            float gdv[3];
            #pragma unroll
            for (int d = 0; d < 3; d++) {
                float l = mn[d], u = mx[d];
                float r = __fdiv_rn(__fsub_rn(u, l), RAD);
                r = fminf(fmaxf(r, 0.0f), 96.0f);
                float gdf = ceilf(r);
                float c = __fmul_rn(__fadd_rn(l, u), 0.5f);
                s_lo[d] = __fsub_rn(c, __fmul_rn(__fmul_rn(gdf, RAD), 0.5f));
                float gd = fmaxf(gdf, 1.0f);
                gdv[d] = gd;
                s_gdm1[d] = gd - 1.0f;
            }
            int g0 = (int)gdv[0], g1 = (int)gdv[1], g2 = (int)gdv[2];
            s_strd[0] = g1 * g2; s_strd[1] = g2; s_strd[2] = 1;
            int ncells = g0 * g1 * g2;
            s_ncells = ncells;
            s_cellbits = (ncells <= 1) ? 0 : (32 - __clz(ncells - 1));
            g_grid[b] = make_int4(g0, g1, g2, 0);
        }
    }
    __syncthreads();

    // --- keys from the SAME registers (no second global pass) ---
    uint32_t tk[4];
    #pragma unroll
    for (int k = 0; k < 4; k++) {
        float co[3];
        co[0] = px[k]; co[1] = py[k]; co[2] = pz[k];
        int flat = 0;
        #pragma unroll
        for (int d = 0; d < 3; d++) {
            float c = floorf(__fdiv_rn(__fsub_rn(co[d], s_lo[d]), RAD));
            c = fminf(fmaxf(c, 0.0f), s_gdm1[d]);
            flat += (int)c * s_strd[d];
        }
        tk[k] = ((uint32_t)flat << 12) | (uint32_t)(t * 4 + k);
    }
    int ncells = s_ncells, cellbits = s_cellbits;
    __syncthreads();

    uint32_t* gk = g_keys + b * Nn;

    if (cellbits == 0) {
        // single cell: blocked order already == stable order
        #pragma unroll
        for (int k = 0; k < 4; k++) gk[t * 4 + k] = tk[k];
        return;
    }

    if (ncells <= MAXC) {
        // ---- fast path: smem counting sort + parallel segment rank ----
        int*      start  = sm->fp.start;
        int*      cursor = sm->fp.cursor;
        uint32_t* skeys  = sm->fp.keys;

        for (int c = t; c < ncells; c += 1024) cursor[c] = 0;
        __syncthreads();
        #pragma unroll
        for (int k = 0; k < 4; k++) atomicAdd(&cursor[tk[k] >> 12], 1);
        __syncthreads();

        // exclusive scan of counts -> start; reset cursor to start
        int items = (ncells + 1023) >> 10;
        int base = t * items;
        int lsum = 0;
        for (int k = 0; k < items; k++) {
            int c = base + k;
            if (c < ncells) lsum += cursor[c];
        }
        int run;
        Scan(sm->fp.scan_ts).ExclusiveSum(lsum, run);
        __syncthreads();
        for (int k = 0; k < items; k++) {
            int c = base + k;
            if (c < ncells) {
                int h = cursor[c];       // count (only this thread touches c)
                start[c]  = run;
                cursor[c] = run;         // scatter cursor
                run += h;
            }
        }
        __syncthreads();

        // scatter into cell segments (order within cell arbitrary)
        #pragma unroll
        for (int k = 0; k < 4; k++) {
            int pos = atomicAdd(&cursor[tk[k] >> 12], 1);
            skeys[pos] = tk[k];
        }
        __syncthreads();   // after this, cursor[c] == segment end

        // parallel rank within segment: independent smem loads, no chains.
        // keys unique -> segstart + (#smaller in segment) is exact stable pos.
        #pragma unroll
        for (int k = 0; k < 4; k++) {
            int p = t * 4 + k;
            uint32_t key = skeys[p];
            int c = (int)(key >> 12);
            int s = start[c], e = cursor[c];
            int r = 0;
            for (int q = s; q < e; q++) r += (skeys[q] < key);
            gk[s + r] = key;
        }
    } else {
        // ---- fallback: CUB radix over cell bits (stable passes) ----
        Sorter(sm->sort_ts).Sort(tk, 12, 12 + cellbits);
        #pragma unroll
        for (int k = 0; k < 4; k++) gk[t * 4 + k] = tk[k];
    }
}

// ---------------------------------------------------------------------------
// Kernel 2: gather by sorted order; write idxs, locs_s, data_s and stash
// float4{x,y,z,|p|^2} (sq computed ONCE, used on both sides of d2).
// ---------------------------------------------------------------------------
__global__ void k_gather(const float* __restrict__ locs,
                         const float* __restrict__ data,
                         float* __restrict__ out) {
    int gid = blockIdx.x * blockDim.x + threadIdx.x;
    if (gid >= Bn * Nn) return;
    int b = gid >> 12;
    int ord = (int)(g_keys[gid] & 4095u);

    const float* lp = locs + (size_t)(b*Nn + ord) * 3;
    float x = lp[0], y = lp[1], z = lp[2];
    float sq = __fadd_rn(__fadd_rn(__fmul_rn(x, x), __fmul_rn(y, y)),
                         __fmul_rn(z, z));
    g_locs[gid] = make_float4(x, y, z, sq);

    out[OFF_IDXS + gid] = (float)ord;
    float* lout = out + OFF_LOCS + (size_t)gid * 3;
    lout[0] = x; lout[1] = y; lout[2] = z;

    const float4* dp = (const float4*)(data + (size_t)(b*Nn + ord) * 16);
    float4* dq = (float4*)(out + OFF_DATA + (size_t)gid * 16);
    #pragma unroll
    for (int q = 0; q < 4; q++) dq[q] = dp[q];
}

// ---------------------------------------------------------------------------
// Kernel 3: neighbor lists with cell pruning. One warp per sorted particle
// (32 particles/block, 256 blocks — the verified-fast R9 config).
// 9 (dx,dy) segments found by parallel binary search on sorted keys; segments
// visited in ascending cell-id (== ascending sorted index) order, realizing
// the reference's "first 128 in-radius, ascending" exactly.
// ---------------------------------------------------------------------------
__global__ void k_neighbors(float* __restrict__ out) {
    extern __shared__ char smem[];
    float4*   shl = (float4*)smem;                 // 65536 B
    uint32_t* shk = (uint32_t*)(smem + Nn * 16);   // 16384 B
    int b    = blockIdx.x >> 7;
    int tile = blockIdx.x & 127;
    const float4*   gl = g_locs + b * Nn;
    const uint32_t* gk = g_keys + b * Nn;
    for (int i = threadIdx.x; i < Nn; i += 1024) { shl[i] = gl[i]; shk[i] = gk[i]; }
    __syncthreads();

    int4 G = g_grid[b];
    int g0 = G.x, g1 = G.y, g2 = G.z;

    int warp = threadIdx.x >> 5;
    int lane = threadIdx.x & 31;
    int i = tile * 32 + warp;

    uint32_t mykey = shk[i];
    int cell = (int)(mykey >> 12);
    int cz = cell % g2;
    int t2 = cell / g2;
    int cy = t2 % g1;
    int cx = t2 / g1;

    // lanes 0..17: binary search the 9 segment bounds (2 per segment)
    int res = 0;
    if (lane < 18) {
        int s  = lane >> 1;
        int dx = s / 3 - 1, dy = s % 3 - 1;
        int nx = cx + dx, ny = cy + dy;
        if (nx >= 0 && nx < g0 && ny >= 0 && ny < g1) {
            int base = (nx * g1 + ny) * g2;
            int zlo = max(cz - 1, 0), zhi = min(cz + 1, g2 - 1);
            uint32_t target = ((uint32_t)((lane & 1) ? (base + zhi + 1)
                                                     : (base + zlo))) << 12;
            int lo = 0, hi = Nn;
            while (lo < hi) {
                int mid = (lo + hi) >> 1;
                if (shk[mid] < target) lo = mid + 1; else hi = mid;
            }
            res = lo;
        }
    }

    float4 me = shl[i];
    float* nout = out + OFF_NBR + (size_t)(b*Nn + i) * Mn;
    unsigned lt = (1u << lane) - 1u;

    int count = 0;
    #pragma unroll 1
    for (int s = 0; s < 9; s++) {
        int lo = __shfl_sync(0xffffffffu, res, 2*s);
        int hi = __shfl_sync(0xffffffffu, res, 2*s + 1);
        for (int j0 = lo; j0 < hi; j0 += 32) {
            int j = j0 + lane;
            bool m = false;
            if (j < hi) {
                float4 o = shl[j];
                float dot = __fadd_rn(__fadd_rn(__fmul_rn(me.x, o.x),
                                                __fmul_rn(me.y, o.y)),
                                      __fmul_rn(me.z, o.z));
                float d2 = __fsub_rn(__fadd_rn(me.w, o.w), __fmul_rn(2.0f, dot));
                m = (d2 <= R2);
            }
            unsigned bal = __ballot_sync(0xffffffffu, m);
            if (m) {
                int pos = count + __popc(bal & lt);
                if (pos < Mn) nout[pos] = (float)j;
            }
            count += __popc(bal);
            if (count >= Mn) goto fill;
        }
    }
fill:
    for (int p = min(count, Mn) + lane; p < Mn; p += 32) nout[p] = -1.0f;
}

// ---------------------------------------------------------------------------
extern "C" void kernel_launch(void* const* d_in, const int* in_sizes, int n_in,
                              void* d_out, int out_size) {
    const float* locs = (const float*)d_in[0];
    const float* data = (const float*)d_in[1];
    float* out = (float*)d_out;

    cudaFuncSetAttribute(k_prep,
                         cudaFuncAttributeMaxDynamicSharedMemorySize,
                         (int)sizeof(PrepSmem));
    cudaFuncSetAttribute(k_neighbors,
                         cudaFuncAttributeMaxDynamicSharedMemorySize,
                         Nn * 16 + Nn * 4);

    k_prep<<<Bn, 1024, sizeof(PrepSmem)>>>(locs);
    k_gather<<<(Bn*Nn + 255) / 256, 256>>>(locs, data, out);
    k_neighbors<<<Bn * (Nn / 32), 1024, Nn * 16 + Nn * 4>>>(out);
}

// round 16
// speedup vs baseline: 2.1572x; 1.0890x over previous
#include <cuda_runtime.h>
#include <cub/cub.cuh>
#include <stdint.h>

#define Bn 2
#define Nn 4096
#define Mn 128
#define RAD 0.1f
#define R2  0.01f
#define MAXC 8192   // fast-path cell-count limit (this input: 1000)

// Output layout (flattened, concatenated in reference return order, all f32)
#define OFF_IDXS 0
#define OFF_NBR  (Bn*Nn)                       // 8192
#define OFF_LOCS (OFF_NBR + Bn*Nn*Mn)          // 1056768
#define OFF_DATA (OFF_LOCS + Bn*Nn*3)          // 1081344

// Scratch (no runtime allocations allowed)
__device__ uint32_t g_keys[Bn*Nn];   // sorted (cell<<12 | idx) per batch
__device__ float4   g_locs[Bn*Nn];   // sorted locs, .w = |p|^2
__device__ int4     g_grid[Bn];      // {g0, g1, g2, unused}

typedef cub::BlockRadixSort<uint32_t, 1024, 4, cub::NullType, 5> Sorter;
typedef cub::BlockScan<int, 1024> Scan;

struct FastPath {
    typename Scan::TempStorage scan_ts;
    int      start[MAXC];    // pristine segment starts
    int      cursor[MAXC];   // hist -> scatter cursor -> segment end
    uint32_t keys[Nn];
};
union PrepSmem {
    typename Sorter::TempStorage sort_ts;   // fallback (ncells > MAXC)
    FastPath fp;
};

// Exact floor((u)/RAD) with rn semantics, division mostly avoided:
// m = rn(u*10) differs from q = rn(u/0.1f) by < 9e-6 for m <= ~96.5
// (two 0.5ulp roundings at ulp(96)=7.6e-6 plus m*1.5e-8). Hence when m is
// >= 1e-4 away from the nearest integer, floor(m) == floor(q) provably;
// otherwise take the exact division path (probability ~2e-4 per op).
__device__ __forceinline__ float cell_floor(float u) {
    float m = __fmul_rn(u, 10.0f);
    float r = rintf(m);
    if (fabsf(__fsub_rn(m, r)) < 1e-4f)
        return floorf(__fdiv_rn(u, RAD));
    return floorf(m);
}

// ---------------------------------------------------------------------------
// Kernel 1: bounds -> grid math (rn-exact, reference-identical) -> packed
// keys -> smem counting sort (hist + scan + atomic scatter + PARALLEL
// rank-in-segment on full unique keys == reference stable argsort).
// Single global read pass; guarded fast-floor replaces most divisions.
// ---------------------------------------------------------------------------
__global__ __launch_bounds__(1024, 1) void k_prep(const float* __restrict__ locs) {
    extern __shared__ char dynsm[];
    PrepSmem* sm = reinterpret_cast<PrepSmem*>(dynsm);

    int b = blockIdx.x;
    const float* L = locs + (size_t)b * Nn * 3;
    int t = threadIdx.x, lane = t & 31, warp = t >> 5;

    __shared__ float wmn[3][32], wmx[3][32];
    __shared__ float s_lo[3], s_gdm1[3];
    __shared__ int   s_strd[3], s_ncells, s_cellbits;

    // --- single coalesced load of this thread's 4 blocked particles ---
    const float4* Lv = (const float4*)L;
    float4 va = Lv[t*3 + 0], vb = Lv[t*3 + 1], vc = Lv[t*3 + 2];
    float px[4] = {va.x, va.w, vb.z, vc.y};
    float py[4] = {va.y, vb.x, vb.w, vc.z};
    float pz[4] = {va.z, vb.y, vc.x, vc.w};

    // --- min/max reduce from registers ---
    float mn[3], mx[3];
    mn[0] = fminf(fminf(px[0], px[1]), fminf(px[2], px[3]));
    mx[0] = fmaxf(fmaxf(px[0], px[1]), fmaxf(px[2], px[3]));
    mn[1] = fminf(fminf(py[0], py[1]), fminf(py[2], py[3]));
    mx[1] = fmaxf(fmaxf(py[0], py[1]), fmaxf(py[2], py[3]));
    mn[2] = fminf(fminf(pz[0], pz[1]), fminf(pz[2], pz[3]));
    mx[2] = fmaxf(fmaxf(pz[0], pz[1]), fmaxf(pz[2], pz[3]));
    #pragma unroll
    for (int o = 16; o; o >>= 1) {
        #pragma unroll
        for (int d = 0; d < 3; d++) {
            mn[d] = fminf(mn[d], __shfl_xor_sync(0xffffffffu, mn[d], o));
            mx[d] = fmaxf(mx[d], __shfl_xor_sync(0xffffffffu, mx[d], o));
        }
    }
    if (lane == 0) {
        #pragma unroll
        for (int d = 0; d < 3; d++) { wmn[d][warp] = mn[d]; wmx[d][warp] = mx[d]; }
    }
    __syncthreads();
    if (t < 32) {
        #pragma unroll
        for (int d = 0; d < 3; d++) { mn[d] = wmn[d][t]; mx[d] = wmx[d][t]; }
        #pragma unroll
        for (int o = 16; o; o >>= 1) {
            #pragma unroll
            for (int d = 0; d < 3; d++) {
                mn[d] = fminf(mn[d], __shfl_xor_sync(0xffffffffu, mn[d], o));
                mx[d] = fmaxf(mx[d], __shfl_xor_sync(0xffffffffu, mx[d], o));
            }
        }
        if (t == 0) {
            float gdv[3];
            #pragma unroll
            for (int d = 0; d < 3; d++) {
                float l = mn[d], u = mx[d];
                float r = __fdiv_rn(__fsub_rn(u, l), RAD);
                r = fminf(fmaxf(r, 0.0f), 96.0f);
                float gdf = ceilf(r);
                float c = __fmul_rn(__fadd_rn(l, u), 0.5f);
                s_lo[d] = __fsub_rn(c, __fmul_rn(__fmul_rn(gdf, RAD), 0.5f));
                float gd = fmaxf(gdf, 1.0f);
                gdv[d] = gd;
                s_gdm1[d] = gd - 1.0f;
            }
            int g0 = (int)gdv[0], g1 = (int)gdv[1], g2 = (int)gdv[2];
            s_strd[0] = g1 * g2; s_strd[1] = g2; s_strd[2] = 1;
            int ncells = g0 * g1 * g2;
            s_ncells = ncells;
            s_cellbits = (ncells <= 1) ? 0 : (32 - __clz(ncells - 1));
            g_grid[b] = make_int4(g0, g1, g2, 0);
        }
    }
    __syncthreads();

    // --- keys from the SAME registers (no second global pass) ---
    uint32_t tk[4];
    #pragma unroll
    for (int k = 0; k < 4; k++) {
        float co[3];
        co[0] = px[k]; co[1] = py[k]; co[2] = pz[k];
        int flat = 0;
        #pragma unroll
        for (int d = 0; d < 3; d++) {
            float c = cell_floor(__fsub_rn(co[d], s_lo[d]));
            c = fminf(fmaxf(c, 0.0f), s_gdm1[d]);
            flat += (int)c * s_strd[d];
        }
        tk[k] = ((uint32_t)flat << 12) | (uint32_t)(t * 4 + k);
    }
    int ncells = s_ncells, cellbits = s_cellbits;
    __syncthreads();

    uint32_t* gk = g_keys + b * Nn;

    if (cellbits == 0) {
        // single cell: blocked order already == stable order
        #pragma unroll
        for (int k = 0; k < 4; k++) gk[t * 4 + k] = tk[k];
        return;
    }

    if (ncells <= MAXC) {
        // ---- fast path: smem counting sort + parallel segment rank ----
        int*      start  = sm->fp.start;
        int*      cursor = sm->fp.cursor;
        uint32_t* skeys  = sm->fp.keys;

        for (int c = t; c < ncells; c += 1024) cursor[c] = 0;
        __syncthreads();
        #pragma unroll
        for (int k = 0; k < 4; k++) atomicAdd(&cursor[tk[k] >> 12], 1);
        __syncthreads();

        // exclusive scan of counts -> start; reset cursor to start
        int items = (ncells + 1023) >> 10;
        int base = t * items;
        int lsum = 0;
        for (int k = 0; k < items; k++) {
            int c = base + k;
            if (c < ncells) lsum += cursor[c];
        }
        int run;
        Scan(sm->fp.scan_ts).ExclusiveSum(lsum, run);
        __syncthreads();
        for (int k = 0; k < items; k++) {
            int c = base + k;
            if (c < ncells) {
                int h = cursor[c];       // count (only this thread touches c)
                start[c]  = run;
                cursor[c] = run;         // scatter cursor
                run += h;
            }
        }
        __syncthreads();

        // scatter into cell segments (order within cell arbitrary)
        #pragma unroll
        for (int k = 0; k < 4; k++) {
            int pos = atomicAdd(&cursor[tk[k] >> 12], 1);
            skeys[pos] = tk[k];
        }
        __syncthreads();   // after this, cursor[c] == segment end

        // parallel rank within segment: independent smem loads, no chains.
        // keys unique -> segstart + (#smaller in segment) is exact stable pos.
        #pragma unroll
        for (int k = 0; k < 4; k++) {
            int p = t * 4 + k;
            uint32_t key = skeys[p];
            int c = (int)(key >> 12);
            int s = start[c], e = cursor[c];
            int r = 0;
            for (int q = s; q < e; q++) r += (skeys[q] < key);
            gk[s + r] = key;
        }
    } else {
        // ---- fallback: CUB radix over cell bits (stable passes) ----
        Sorter(sm->sort_ts).Sort(tk, 12, 12 + cellbits);
        #pragma unroll
        for (int k = 0; k < 4; k++) gk[t * 4 + k] = tk[k];
    }
}

// ---------------------------------------------------------------------------
// Kernel 2: gather by sorted order; write idxs, locs_s, data_s and stash
// float4{x,y,z,|p|^2} (sq computed ONCE, used on both sides of d2).
// ---------------------------------------------------------------------------
__global__ void k_gather(const float* __restrict__ locs,
                         const float* __restrict__ data,
                         float* __restrict__ out) {
    int gid = blockIdx.x * blockDim.x + threadIdx.x;
    if (gid >= Bn * Nn) return;
    int b = gid >> 12;
    int ord = (int)(g_keys[gid] & 4095u);

    const float* lp = locs + (size_t)(b*Nn + ord) * 3;
    float x = lp[0], y = lp[1], z = lp[2];
    float sq = __fadd_rn(__fadd_rn(__fmul_rn(x, x), __fmul_rn(y, y)),
                         __fmul_rn(z, z));
    g_locs[gid] = make_float4(x, y, z, sq);

    out[OFF_IDXS + gid] = (float)ord;
    float* lout = out + OFF_LOCS + (size_t)gid * 3;
    lout[0] = x; lout[1] = y; lout[2] = z;

    const float4* dp = (const float4*)(data + (size_t)(b*Nn + ord) * 16);
    float4* dq = (float4*)(out + OFF_DATA + (size_t)gid * 16);
    #pragma unroll
    for (int q = 0; q < 4; q++) dq[q] = dp[q];
}

// ---------------------------------------------------------------------------
// Kernel 3: neighbor lists with cell pruning, SMEM-FREE. One warp per sorted
// particle, 8 warps/block (256 thr, 1024 blocks). g_locs/g_keys are 96KB per
// batch -> L1-resident; binary searches and segment scans read via __ldg.
// Same arithmetic and visit order as the verified smem version -> outputs
// byte-identical ("first 128 in-radius, ascending sorted index").
// ---------------------------------------------------------------------------
__global__ __launch_bounds__(256) void k_neighbors(float* __restrict__ out) {
    int gwarp = (blockIdx.x * 256 + threadIdx.x) >> 5;   // 0 .. Bn*Nn/32*8-1
    int lane  = threadIdx.x & 31;
    int b = gwarp >> 12;            // 4096 warps per batch
    int i = gwarp & 4095;

    const float4*   shl = g_locs + b * Nn;
    const uint32_t* shk = g_keys + b * Nn;

    int4 G = g_grid[b];
    int g0 = G.x, g1 = G.y, g2 = G.z;

    uint32_t mykey = __ldg(&shk[i]);
    int cell = (int)(mykey >> 12);
    int cz = cell % g2;
    int t2 = cell / g2;
    int cy = t2 % g1;
    int cx = t2 / g1;

    // lanes 0..17: binary search the 9 segment bounds (2 per segment)
    int res = 0;
    if (lane < 18) {
        int s  = lane >> 1;
        int dx = s / 3 - 1, dy = s % 3 - 1;
        int nx = cx + dx, ny = cy + dy;
        if (nx >= 0 && nx < g0 && ny >= 0 && ny < g1) {
            int base = (nx * g1 + ny) * g2;
            int zlo = max(cz - 1, 0), zhi = min(cz + 1, g2 - 1);
            uint32_t target = ((uint32_t)((lane & 1) ? (base + zhi + 1)
                                                     : (base + zlo))) << 12;
            int lo = 0, hi = Nn;
            while (lo < hi) {
                int mid = (lo + hi) >> 1;
                if (__ldg(&shk[mid]) < target) lo = mid + 1; else hi = mid;
            }
            res = lo;
        }
    }

    float4 me = __ldg(&shl[i]);
    float* nout = out + OFF_NBR + (size_t)(b*Nn + i) * Mn;
    unsigned lt = (1u << lane) - 1u;

    int count = 0;
    #pragma unroll 1
    for (int s = 0; s < 9; s++) {
        int lo = __shfl_sync(0xffffffffu, res, 2*s);
        int hi = __shfl_sync(0xffffffffu, res, 2*s + 1);
        for (int j0 = lo; j0 < hi; j0 += 32) {
            int j = j0 + lane;
            bool m = false;
            if (j < hi) {
                float4 o = __ldg(&shl[j]);
                float dot = __fadd_rn(__fadd_rn(__fmul_rn(me.x, o.x),
                                                __fmul_rn(me.y, o.y)),
                                      __fmul_rn(me.z, o.z));
                float d2 = __fsub_rn(__fadd_rn(me.w, o.w), __fmul_rn(2.0f, dot));
                m = (d2 <= R2);
            }
            unsigned bal = __ballot_sync(0xffffffffu, m);
            if (m) {
                int pos = count + __popc(bal & lt);
                if (pos < Mn) nout[pos] = (float)j;
            }
            count += __popc(bal);
            if (count >= Mn) goto fill;
        }
    }
fill:
    for (int p = min(count, Mn) + lane; p < Mn; p += 32) nout[p] = -1.0f;
}

// ---------------------------------------------------------------------------
extern "C" void kernel_launch(void* const* d_in, const int* in_sizes, int n_in,
                              void* d_out, int out_size) {
    const float* locs = (const float*)d_in[0];
    const float* data = (const float*)d_in[1];
    float* out = (float*)d_out;

    cudaFuncSetAttribute(k_prep,
                         cudaFuncAttributeMaxDynamicSharedMemorySize,
                         (int)sizeof(PrepSmem));

    k_prep<<<Bn, 1024, sizeof(PrepSmem)>>>(locs);
    k_gather<<<(Bn*Nn + 255) / 256, 256>>>(locs, data, out);
    k_neighbors<<<Bn * Nn / 8, 256>>>(out);
}